// round 15
// baseline (speedup 1.0000x reference)
#include <cuda_runtime.h>
#include <math.h>

#define NJ 7
#define DT_ 0.01f
#define GRAV_ 9.81f
#define TPB 64

typedef unsigned long long u64;

// ---- packed f32x2 primitives ----
__device__ __forceinline__ u64 fpk(float lo, float hi) {
    u64 r; asm("mov.b64 %0, {%1, %2};" : "=l"(r) : "f"(lo), "f"(hi)); return r;
}
__device__ __forceinline__ void fup(u64 a, float& lo, float& hi) {
    asm("mov.b64 {%0, %1}, %2;" : "=f"(lo), "=f"(hi) : "l"(a));
}
__device__ __forceinline__ u64 f2add(u64 a, u64 b) {
    u64 r; asm("add.rn.f32x2 %0, %1, %2;" : "=l"(r) : "l"(a), "l"(b)); return r;
}
__device__ __forceinline__ u64 f2mul(u64 a, u64 b) {
    u64 r; asm("mul.rn.f32x2 %0, %1, %2;" : "=l"(r) : "l"(a), "l"(b)); return r;
}
__device__ __forceinline__ u64 f2fma(u64 a, u64 b, u64 c) {
    u64 r; asm("fma.rn.f32x2 %0, %1, %2, %3;" : "=l"(r) : "l"(a), "l"(b), "l"(c)); return r;
}
// a - b == fma(b, (-1,-1), a): exact
__device__ __forceinline__ u64 f2sub(u64 a, u64 b) {
    const u64 m1 = 0xBF800000BF800000ULL;
    return f2fma(b, m1, a);
}

__device__ __forceinline__ u64 dot3(const u64* a, const u64* b) {
    return f2fma(a[0], b[0], f2fma(a[1], b[1], f2mul(a[2], b[2])));
}
__device__ __forceinline__ void cross3(const u64* a, const u64* b, u64* o) {
    o[0] = f2sub(f2mul(a[1], b[2]), f2mul(a[2], b[1]));
    o[1] = f2sub(f2mul(a[2], b[0]), f2mul(a[0], b[2]));
    o[2] = f2sub(f2mul(a[0], b[1]), f2mul(a[1], b[0]));
}
__device__ __forceinline__ void mat3v(const u64* A, const u64* x, u64* y) {
    y[0] = f2fma(A[0], x[0], f2fma(A[1], x[1], f2mul(A[2], x[2])));
    y[1] = f2fma(A[3], x[0], f2fma(A[4], x[1], f2mul(A[5], x[2])));
    y[2] = f2fma(A[6], x[0], f2fma(A[7], x[1], f2mul(A[8], x[2])));
}
__device__ __forceinline__ void mat3tv(const u64* A, const u64* x, u64* y) {
    y[0] = f2fma(A[0], x[0], f2fma(A[3], x[1], f2mul(A[6], x[2])));
    y[1] = f2fma(A[1], x[0], f2fma(A[4], x[1], f2mul(A[7], x[2])));
    y[2] = f2fma(A[2], x[0], f2fma(A[5], x[1], f2mul(A[8], x[2])));
}
// out = Xup*in, Xup=[[A,0],[-A*S(p),A]]; in=(w;l): out = (A w ; A (l - p x w))
__device__ __forceinline__ void applyXup(const u64* A, const u64* p, const u64* in, u64* out) {
    u64 pxw[3];
    cross3(p, in, pxw);
    u64 t[3] = { f2sub(in[3], pxw[0]), f2sub(in[4], pxw[1]), f2sub(in[5], pxw[2]) };
    mat3v(A, in, out);
    mat3v(A, t, out + 3);
}
// out = Xup^T*in, in=(n;f): out = (A^T n + p x (A^T f) ; A^T f)
__device__ __forceinline__ void applyXupT(const u64* A, const u64* p, const u64* in, u64* out) {
    u64 t[3], n[3], pxt[3];
    mat3tv(A, in + 3, t);
    mat3tv(A, in, n);
    cross3(p, t, pxt);
    out[0] = f2add(n[0], pxt[0]);
    out[1] = f2add(n[1], pxt[1]);
    out[2] = f2add(n[2], pxt[2]);
    out[3] = t[0]; out[4] = t[1]; out[5] = t[2];
}
// symmetric 3x3 packed (xx,xy,xz,yy,yz,zz) * vec
__device__ __forceinline__ void sym3v(const u64* J, const u64* x, u64* y) {
    y[0] = f2fma(J[0], x[0], f2fma(J[1], x[1], f2mul(J[2], x[2])));
    y[1] = f2fma(J[1], x[0], f2fma(J[3], x[1], f2mul(J[4], x[2])));
    y[2] = f2fma(J[2], x[0], f2fma(J[4], x[1], f2mul(J[5], x[2])));
}

// constants per joint (PRE-DUPLICATED (v,v) u64): ax3, p3, E9, Ibar6, hb3, m1 = 25
#define JSTRIDE 25
#define OFF_AX 0
#define OFF_P  3
#define OFF_E  6
#define OFF_IB 15
#define OFF_HB 21
#define OFF_M  24

// lower-triangle index for Mm
#define TRI(i, j) ((i) * ((i) + 1) / 2 + (j))

__global__ void __launch_bounds__(TPB)
panda_dyn_kernel(const float* __restrict__ x, const float* __restrict__ u,
                 const float* __restrict__ axes, const float* __restrict__ Rtree,
                 const float* __restrict__ ptree, const float* __restrict__ Isp,
                 float* __restrict__ out, int B)
{
    __shared__ u64 sJ[NJ * JSTRIDE];
    __shared__ u64 sF[NJ * 6][TPB];    // per-thread staged body forces (write-once/read-once)
    __shared__ u64 sMm[28][TPB];       // per-thread staged M lower triangle

    if (threadIdx.x < NJ) {
        int i = threadIdx.x;
        u64* d = &sJ[i * JSTRIDE];
        float v;
        v = axes[3*i + 0]; d[OFF_AX + 0] = fpk(v, v);
        v = axes[3*i + 1]; d[OFF_AX + 1] = fpk(v, v);
        v = axes[3*i + 2]; d[OFF_AX + 2] = fpk(v, v);
        v = ptree[3*i + 0]; d[OFF_P + 0] = fpk(v, v);
        v = ptree[3*i + 1]; d[OFF_P + 1] = fpk(v, v);
        v = ptree[3*i + 2]; d[OFF_P + 2] = fpk(v, v);
        #pragma unroll
        for (int k = 0; k < 9; k++) { v = Rtree[9*i + k]; d[OFF_E + k] = fpk(v, v); }
        const float* Im = &Isp[36 * i];
        v = Im[0];      d[OFF_IB + 0] = fpk(v, v);
        v = Im[1];      d[OFF_IB + 1] = fpk(v, v);
        v = Im[2];      d[OFF_IB + 2] = fpk(v, v);
        v = Im[7];      d[OFF_IB + 3] = fpk(v, v);
        v = Im[8];      d[OFF_IB + 4] = fpk(v, v);
        v = Im[14];     d[OFF_IB + 5] = fpk(v, v);
        v = Im[2*6+4];  d[OFF_HB + 0] = fpk(v, v);
        v = Im[0*6+5];  d[OFF_HB + 1] = fpk(v, v);
        v = Im[1*6+3];  d[OFF_HB + 2] = fpk(v, v);
        v = Im[3*6+3];  d[OFF_M]      = fpk(v, v);
    }
    __syncthreads();

    int t = blockIdx.x * TPB + threadIdx.x;
    if (2 * t >= B) return;
    int tid = threadIdx.x;

    const float QL[NJ] = {-2.9671f, -1.8326f, -2.9671f, -3.1416f, -2.9671f, -0.0873f, -2.9671f};
    const float QU[NJ] = { 2.9671f,  1.8326f,  2.9671f,  0.0f,     2.9671f,  3.8223f,  2.9671f};

    const u64 DT2 = fpk(DT_, DT_);
    const u64 E8  = fpk(1e-8f, 1e-8f);
    const u64 G2  = fpk(GRAV_, GRAV_);

    // ---- coalesced loads: rows 2t,2t+1 of x (7x float4) / u (7x float2) ----
    float xl[28];
    {
        const float4* xp = (const float4*)(x + 28ull * (size_t)t);
        #pragma unroll
        for (int k = 0; k < 7; k++) {
            float4 v = xp[k];
            xl[4*k+0] = v.x; xl[4*k+1] = v.y; xl[4*k+2] = v.z; xl[4*k+3] = v.w;
        }
    }
    float ul[14];
    {
        const float2* up = (const float2*)(u + 14ull * (size_t)t);
        #pragma unroll
        for (int k = 0; k < 7; k++) { float2 v = up[k]; ul[2*k] = v.x; ul[2*k+1] = v.y; }
    }

    u64 q2[NJ], qd2[NJ], bb2[NJ];
    float ql[NJ], qh[NJ];
    #pragma unroll
    for (int i = 0; i < NJ; i++) {
        ql[i] = fminf(fmaxf(xl[i],      QL[i]), QU[i]);
        qh[i] = fminf(fmaxf(xl[14 + i], QL[i]), QU[i]);
        q2[i]  = fpk(ql[i], qh[i]);
        qd2[i] = fpk(xl[7 + i], xl[21 + i]);
        bb2[i] = fpk(ul[i], ul[7 + i]);
    }

    // ---- joint transforms: A_i = R(q_i)^T * R_tree[i], packed ----
    u64 A2[NJ][9];
    #pragma unroll
    for (int i = 0; i < NJ; i++) {
        const u64* ax = &sJ[i*JSTRIDE + OFF_AX];
        const u64* E  = &sJ[i*JSTRIDE + OFF_E];
        float sl, cl, sh, ch;
        __sincosf(ql[i], &sl, &cl);
        __sincosf(qh[i], &sh, &ch);
        u64 s2 = fpk(sl, sh);
        u64 c2 = fpk(cl, ch);
        u64 oc = f2sub(fpk(1.0f, 1.0f), c2);
        u64 R[9];
        R[0] = f2fma(oc, f2mul(ax[0], ax[0]), c2);
        R[1] = f2sub(f2mul(oc, f2mul(ax[0], ax[1])), f2mul(s2, ax[2]));
        R[2] = f2fma(s2, ax[1], f2mul(oc, f2mul(ax[0], ax[2])));
        R[3] = f2fma(s2, ax[2], f2mul(oc, f2mul(ax[1], ax[0])));
        R[4] = f2fma(oc, f2mul(ax[1], ax[1]), c2);
        R[5] = f2sub(f2mul(oc, f2mul(ax[1], ax[2])), f2mul(s2, ax[0]));
        R[6] = f2sub(f2mul(oc, f2mul(ax[2], ax[0])), f2mul(s2, ax[1]));
        R[7] = f2fma(s2, ax[0], f2mul(oc, f2mul(ax[2], ax[1])));
        R[8] = f2fma(oc, f2mul(ax[2], ax[2]), c2);
        #pragma unroll
        for (int r = 0; r < 3; r++)
        #pragma unroll
            for (int cc = 0; cc < 3; cc++)
                A2[i][3*r + cc] = f2fma(R[r], E[cc],
                                    f2fma(R[3 + r], E[3 + cc], f2mul(R[6 + r], E[6 + cc])));
    }

    // ---- RNEA forward pass (qdd=0): per-body forces staged to smem ----
    u64 pv[6], pa[6];
    #pragma unroll
    for (int i = 0; i < NJ; i++) {
        const u64* ax = &sJ[i*JSTRIDE + OFF_AX];
        const u64* p  = &sJ[i*JSTRIDE + OFF_P];
        const u64* Ib = &sJ[i*JSTRIDE + OFF_IB];
        const u64* hb = &sJ[i*JSTRIDE + OFF_HB];
        u64 m2 = sJ[i*JSTRIDE + OFF_M];
        const u64* Am = A2[i];
        u64 xv[6], xa[6];
        if (i == 0) {   // pv = 0, pa = (0,0,0,0,0,G): folded by hand
            #pragma unroll
            for (int k = 0; k < 6; k++) xv[k] = 0ULL;
            xa[0] = 0ULL; xa[1] = 0ULL; xa[2] = 0ULL;
            xa[3] = f2mul(G2, Am[2]); xa[4] = f2mul(G2, Am[5]); xa[5] = f2mul(G2, Am[8]);
        } else {
            applyXup(Am, p, pv, xv);
            applyXup(Am, p, pa, xa);
        }
        u64 wJ[3] = { f2mul(ax[0], qd2[i]), f2mul(ax[1], qd2[i]), f2mul(ax[2], qd2[i]) };
        u64 v6[6] = { f2add(xv[0], wJ[0]), f2add(xv[1], wJ[1]), f2add(xv[2], wJ[2]),
                      xv[3], xv[4], xv[5] };
        u64 cw[3], cl3[3];
        if (i == 0) {
            cw[0] = cw[1] = cw[2] = 0ULL;
            cl3[0] = cl3[1] = cl3[2] = 0ULL;
        } else {
            cross3(v6, wJ, cw);
            cross3(v6 + 3, wJ, cl3);
        }
        u64 a6[6] = { f2add(xa[0], cw[0]),  f2add(xa[1], cw[1]),  f2add(xa[2], cw[2]),
                      f2add(xa[3], cl3[0]), f2add(xa[4], cl3[1]), f2add(xa[5], cl3[2]) };
        // I v = (Ib w + hb x l ; m l - hb x w)
        u64 Ivn[3], Ivf[3], t1[3], t2[3];
        sym3v(Ib, v6, Ivn);
        cross3(hb, v6 + 3, t1);
        cross3(hb, v6, t2);
        #pragma unroll
        for (int k = 0; k < 3; k++) {
            Ivn[k] = f2add(Ivn[k], t1[k]);
            Ivf[k] = f2sub(f2mul(m2, v6[3 + k]), t2[k]);
        }
        u64 Ian[3], Iaf[3];
        sym3v(Ib, a6, Ian);
        cross3(hb, a6 + 3, t1);
        cross3(hb, a6, t2);
        #pragma unroll
        for (int k = 0; k < 3; k++) {
            Ian[k] = f2add(Ian[k], t1[k]);
            Iaf[k] = f2sub(f2mul(m2, a6[3 + k]), t2[k]);
        }
        // f = Ia + (w x Ivn + l x Ivf ; w x Ivf) -> staged to shared
        u64 c1[3], c2a[3], c3[3];
        cross3(v6, Ivn, c1);
        cross3(v6 + 3, Ivf, c2a);
        cross3(v6, Ivf, c3);
        #pragma unroll
        for (int k = 0; k < 3; k++) {
            sF[i*6 + k][tid]     = f2add(Ian[k], f2add(c1[k], c2a[k]));
            sF[i*6 + 3 + k][tid] = f2add(Iaf[k], c3[k]);
        }
        #pragma unroll
        for (int k = 0; k < 6; k++) { pv[k] = v6[k]; pa[k] = a6[k]; }
    }

    // ---- backward pass: bb = tau - h; child contribution carried in regs ----
    {
        u64 carry[6];
        #pragma unroll
        for (int i = NJ - 1; i >= 0; i--) {
            const u64* ax = &sJ[i*JSTRIDE + OFF_AX];
            u64 ftot[6];
            #pragma unroll
            for (int k = 0; k < 6; k++) {
                u64 own = sF[i*6 + k][tid];
                ftot[k] = (i == NJ - 1) ? own : f2add(own, carry[k]);
            }
            bb2[i] = f2sub(bb2[i], dot3(ax, ftot));
            if (i > 0)
                applyXupT(A2[i], &sJ[i*JSTRIDE + OFF_P], ftot, carry);
        }
    }

    // ---- CRBA (10-param composite inertia), M staged to smem ----
    u64 Jc[6], hc[3], mc2;
    {
        const u64* Ib = &sJ[(NJ-1)*JSTRIDE + OFF_IB];
        const u64* hb = &sJ[(NJ-1)*JSTRIDE + OFF_HB];
        #pragma unroll
        for (int k = 0; k < 6; k++) Jc[k] = Ib[k];
        #pragma unroll
        for (int k = 0; k < 3; k++) hc[k] = hb[k];
        mc2 = sJ[(NJ-1)*JSTRIDE + OFF_M];
    }
    const u64 TWO = fpk(2.0f, 2.0f);
    #pragma unroll
    for (int i = NJ - 1; i >= 0; i--) {
        const u64* ax = &sJ[i*JSTRIDE + OFF_AX];
        u64 F[6];
        sym3v(Jc, ax, F);
        cross3(ax, hc, F + 3);
        sMm[TRI(i, i)][tid] = f2add(dot3(ax, F), E8);
        #pragma unroll
        for (int j = i - 1; j >= 0; j--) {
            u64 o6[6];
            applyXupT(A2[j+1], &sJ[(j+1)*JSTRIDE + OFF_P], F, o6);
            #pragma unroll
            for (int r = 0; r < 6; r++) F[r] = o6[r];
            const u64* aj = &sJ[j*JSTRIDE + OFF_AX];
            sMm[TRI(i, j)][tid] = dot3(aj, F);
        }
        if (i > 0) {
            const u64* p  = &sJ[i*JSTRIDE + OFF_P];
            const u64* Am = A2[i];
            u64 hp[3];
            mat3tv(Am, hc, hp);
            u64 T[9];
            #pragma unroll
            for (int cc = 0; cc < 3; cc++) {
                T[0*3+cc] = f2fma(Jc[0], Am[cc], f2fma(Jc[1], Am[3+cc], f2mul(Jc[2], Am[6+cc])));
                T[1*3+cc] = f2fma(Jc[1], Am[cc], f2fma(Jc[3], Am[3+cc], f2mul(Jc[4], Am[6+cc])));
                T[2*3+cc] = f2fma(Jc[2], Am[cc], f2fma(Jc[4], Am[3+cc], f2mul(Jc[5], Am[6+cc])));
            }
            u64 Jp[6];
            Jp[0] = f2fma(Am[0], T[0], f2fma(Am[3], T[3], f2mul(Am[6], T[6])));
            Jp[1] = f2fma(Am[0], T[1], f2fma(Am[3], T[4], f2mul(Am[6], T[7])));
            Jp[2] = f2fma(Am[0], T[2], f2fma(Am[3], T[5], f2mul(Am[6], T[8])));
            Jp[3] = f2fma(Am[1], T[1], f2fma(Am[4], T[4], f2mul(Am[7], T[7])));
            Jp[4] = f2fma(Am[1], T[2], f2fma(Am[4], T[5], f2mul(Am[7], T[8])));
            Jp[5] = f2fma(Am[2], T[2], f2fma(Am[5], T[5], f2mul(Am[8], T[8])));
            u64 hdp  = dot3(hp, p);
            u64 pp   = dot3(p, p);
            u64 diag = f2fma(mc2, pp, f2mul(TWO, hdp));
            u64 d0 = f2fma(mc2, p[0], hp[0]);
            u64 d1 = f2fma(mc2, p[1], hp[1]);
            u64 d2 = f2fma(mc2, p[2], hp[2]);
            const u64* Ibp = &sJ[(i-1)*JSTRIDE + OFF_IB];
            const u64* hbp = &sJ[(i-1)*JSTRIDE + OFF_HB];
            Jc[0] = f2sub(f2add(f2add(Ibp[0], Jp[0]), diag), f2mul(p[0], f2add(hp[0], d0)));
            Jc[1] = f2sub(f2sub(f2add(Ibp[1], Jp[1]), f2mul(p[0], hp[1])), f2mul(p[1], d0));
            Jc[2] = f2sub(f2sub(f2add(Ibp[2], Jp[2]), f2mul(p[0], hp[2])), f2mul(p[2], d0));
            Jc[3] = f2sub(f2add(f2add(Ibp[3], Jp[3]), diag), f2mul(p[1], f2add(hp[1], d1)));
            Jc[4] = f2sub(f2sub(f2add(Ibp[4], Jp[4]), f2mul(p[1], hp[2])), f2mul(p[2], d1));
            Jc[5] = f2sub(f2add(f2add(Ibp[5], Jp[5]), diag), f2mul(p[2], f2add(hp[2], d2)));
            hc[0] = f2add(hbp[0], d0);
            hc[1] = f2add(hbp[1], d1);
            hc[2] = f2add(hbp[2], d2);
            mc2 = f2add(mc2, sJ[(i-1)*JSTRIDE + OFF_M]);
        }
    }

    // ---- GE: reload M into registers (A2 is dead now) and solve ----
    u64 Mm2[NJ][NJ];
    #pragma unroll
    for (int i = 0; i < NJ; i++)
        #pragma unroll
        for (int j = 0; j <= i; j++)
            Mm2[i][j] = sMm[TRI(i, j)][tid];

    u64 invd[NJ];
    #pragma unroll
    for (int k = 0; k < NJ; k++) {
        float dl, dh;
        fup(Mm2[k][k], dl, dh);
        invd[k] = fpk(__fdividef(1.0f, dl), __fdividef(1.0f, dh));
        #pragma unroll
        for (int r = k + 1; r < NJ; r++) {
            u64 fkt = f2mul(Mm2[r][k], invd[k]);
            #pragma unroll
            for (int c2 = k + 1; c2 <= r; c2++)
                Mm2[r][c2] = f2sub(Mm2[r][c2], f2mul(fkt, Mm2[c2][k]));
            bb2[r] = f2sub(bb2[r], f2mul(fkt, bb2[k]));
        }
    }
    u64 qdd2[NJ];
    #pragma unroll
    for (int k = NJ - 1; k >= 0; k--) {
        u64 tt = bb2[k];
        #pragma unroll
        for (int c2 = k + 1; c2 < NJ; c2++)
            tt = f2sub(tt, f2mul(Mm2[c2][k], qdd2[c2]));
        qdd2[k] = f2mul(tt, invd[k]);
    }

    // ---- integrate & coalesced store ----
    float s0[14], s1[14];
    #pragma unroll
    for (int k = 0; k < NJ; k++) {
        u64 qdn = f2fma(DT2, qdd2[k], qd2[k]);
        u64 qn  = f2fma(DT2, qdn, q2[k]);
        fup(qn,  s0[k],     s1[k]);
        fup(qdn, s0[7 + k], s1[7 + k]);
    }
    float4* op = (float4*)(out + 28ull * (size_t)t);
    op[0] = make_float4(s0[0],  s0[1],  s0[2],  s0[3]);
    op[1] = make_float4(s0[4],  s0[5],  s0[6],  s0[7]);
    op[2] = make_float4(s0[8],  s0[9],  s0[10], s0[11]);
    op[3] = make_float4(s0[12], s0[13], s1[0],  s1[1]);
    op[4] = make_float4(s1[2],  s1[3],  s1[4],  s1[5]);
    op[5] = make_float4(s1[6],  s1[7],  s1[8],  s1[9]);
    op[6] = make_float4(s1[10], s1[11], s1[12], s1[13]);
}

extern "C" void kernel_launch(void* const* d_in, const int* in_sizes, int n_in,
                              void* d_out, int out_size) {
    const float* x     = (const float*)d_in[0];
    const float* u     = (const float*)d_in[1];
    const float* axes  = (const float*)d_in[2];
    const float* Rtree = (const float*)d_in[3];
    const float* ptree = (const float*)d_in[4];
    const float* Isp   = (const float*)d_in[5];
    float* out = (float*)d_out;

    int B = in_sizes[0] / 14;         // 65536 (even)
    int nPairs = B / 2;
    int blocks = (nPairs + TPB - 1) / TPB;
    panda_dyn_kernel<<<blocks, TPB>>>(x, u, axes, Rtree, ptree, Isp, out, B);
}

// round 17
// speedup vs baseline: 1.3299x; 1.3299x over previous
#include <cuda_runtime.h>
#include <math.h>

#define NJ 7
#define DT_ 0.01f
#define GRAV_ 9.81f
#define TPB 64

__device__ __forceinline__ void cross3(const float* a, const float* b, float* o) {
    o[0] = a[1]*b[2] - a[2]*b[1];
    o[1] = a[2]*b[0] - a[0]*b[2];
    o[2] = a[0]*b[1] - a[1]*b[0];
}
__device__ __forceinline__ void mat3v(const float* A, const float* x, float* y) {
    y[0] = A[0]*x[0] + A[1]*x[1] + A[2]*x[2];
    y[1] = A[3]*x[0] + A[4]*x[1] + A[5]*x[2];
    y[2] = A[6]*x[0] + A[7]*x[1] + A[8]*x[2];
}
__device__ __forceinline__ void mat3tv(const float* A, const float* x, float* y) {
    y[0] = A[0]*x[0] + A[3]*x[1] + A[6]*x[2];
    y[1] = A[1]*x[0] + A[4]*x[1] + A[7]*x[2];
    y[2] = A[2]*x[0] + A[5]*x[1] + A[8]*x[2];
}
// out = Xup * in, Xup = [[A,0],[-A*S(p),A]]; in=(w;l): out = (A w ; A (l - p x w))
__device__ __forceinline__ void applyXup(const float* A, const float* p, const float* in, float* out) {
    float pxw[3];
    cross3(p, in, pxw);
    float t[3] = { in[3] - pxw[0], in[4] - pxw[1], in[5] - pxw[2] };
    mat3v(A, in, out);
    mat3v(A, t, out + 3);
}
// out = Xup^T * in, in=(n;f): out = (A^T n + p x (A^T f) ; A^T f)
__device__ __forceinline__ void applyXupT(const float* A, const float* p, const float* in, float* out) {
    float t[3], n[3], pxt[3];
    mat3tv(A, in + 3, t);
    mat3tv(A, in, n);
    cross3(p, t, pxt);
    out[0] = n[0] + pxt[0];
    out[1] = n[1] + pxt[1];
    out[2] = n[2] + pxt[2];
    out[3] = t[0]; out[4] = t[1]; out[5] = t[2];
}
// symmetric 3x3 (packed xx,xy,xz,yy,yz,zz) times vector
__device__ __forceinline__ void sym3v(const float* J, const float* x, float* y) {
    y[0] = J[0]*x[0] + J[1]*x[1] + J[2]*x[2];
    y[1] = J[1]*x[0] + J[3]*x[1] + J[4]*x[2];
    y[2] = J[2]*x[0] + J[4]*x[1] + J[5]*x[2];
}

// smem layout per joint: ax3, p3, E9, Ibar6(xx,xy,xz,yy,yz,zz), hb3, m1 = 25 floats
#define JSTRIDE 25
#define OFF_AX 0
#define OFF_P  3
#define OFF_E  6
#define OFF_IB 15
#define OFF_HB 21
#define OFF_M  24

__global__ void __launch_bounds__(TPB, 6)
panda_dyn_kernel(const float* __restrict__ x, const float* __restrict__ u,
                 const float* __restrict__ axes, const float* __restrict__ Rtree,
                 const float* __restrict__ ptree, const float* __restrict__ Isp,
                 float* __restrict__ out, int B)
{
    __shared__ float sJ[NJ * JSTRIDE];

    // stage + structure-extract constants (one joint per thread, NJ threads)
    if (threadIdx.x < NJ) {
        int i = threadIdx.x;
        float* d = &sJ[i * JSTRIDE];
        d[OFF_AX + 0] = axes[3*i + 0];
        d[OFF_AX + 1] = axes[3*i + 1];
        d[OFF_AX + 2] = axes[3*i + 2];
        d[OFF_P + 0] = ptree[3*i + 0];
        d[OFF_P + 1] = ptree[3*i + 1];
        d[OFF_P + 2] = ptree[3*i + 2];
        #pragma unroll
        for (int k = 0; k < 9; k++) d[OFF_E + k] = Rtree[9*i + k];
        const float* Im = &Isp[36 * i];
        d[OFF_IB + 0] = Im[0];   // xx
        d[OFF_IB + 1] = Im[1];   // xy
        d[OFF_IB + 2] = Im[2];   // xz
        d[OFF_IB + 3] = Im[7];   // yy
        d[OFF_IB + 4] = Im[8];   // yz
        d[OFF_IB + 5] = Im[14];  // zz
        // top-right block = skew(hb): [[0,-hz,hy],[hz,0,-hx],[-hy,hx,0]] at cols 3..5
        d[OFF_HB + 0] = Im[2*6 + 4];  // hx
        d[OFF_HB + 1] = Im[0*6 + 5];  // hy
        d[OFF_HB + 2] = Im[1*6 + 3];  // hz
        d[OFF_M] = Im[3*6 + 3];       // m
    }
    __syncthreads();

    int b = blockIdx.x * blockDim.x + threadIdx.x;
    if (b >= B) return;

    const float QL[NJ] = {-2.9671f, -1.8326f, -2.9671f, -3.1416f, -2.9671f, -0.0873f, -2.9671f};
    const float QU[NJ] = { 2.9671f,  1.8326f,  2.9671f,  0.0f,     2.9671f,  3.8223f,  2.9671f};

    float q[NJ], qd[NJ], bb[NJ];
#pragma unroll
    for (int i = 0; i < NJ; i++) {
        q[i]  = fminf(fmaxf(x[b * 14 + i], QL[i]), QU[i]);
        qd[i] = x[b * 14 + 7 + i];
        bb[i] = u[b * 7 + i];          // will become tau - h
    }

    // ---- joint transforms: A_i = R(q_i)^T * R_tree[i] ----
    float A[NJ][9];
#pragma unroll
    for (int i = 0; i < NJ; i++) {
        const float* ax = &sJ[i*JSTRIDE + OFF_AX];
        const float* E  = &sJ[i*JSTRIDE + OFF_E];
        float s, c;
        __sincosf(q[i], &s, &c);
        float oc = 1.0f - c;
        float R[9];
        R[0] = c + oc * ax[0] * ax[0];
        R[1] = -s * ax[2] + oc * ax[0] * ax[1];
        R[2] =  s * ax[1] + oc * ax[0] * ax[2];
        R[3] =  s * ax[2] + oc * ax[1] * ax[0];
        R[4] = c + oc * ax[1] * ax[1];
        R[5] = -s * ax[0] + oc * ax[1] * ax[2];
        R[6] = -s * ax[1] + oc * ax[2] * ax[0];
        R[7] =  s * ax[0] + oc * ax[2] * ax[1];
        R[8] = c + oc * ax[2] * ax[2];
#pragma unroll
        for (int r = 0; r < 3; r++)
#pragma unroll
            for (int cc = 0; cc < 3; cc++)
                A[i][3*r + cc] = R[r] * E[cc] + R[3 + r] * E[3 + cc] + R[6 + r] * E[6 + cc];
    }

    // ---- RNEA forward pass (qdd = 0) with structured inertias ----
    float fw[NJ][3], fv[NJ][3];
    float pv[6] = {0.f, 0.f, 0.f, 0.f, 0.f, 0.f};
    float pa[6] = {0.f, 0.f, 0.f, 0.f, 0.f, GRAV_};
#pragma unroll
    for (int i = 0; i < NJ; i++) {
        const float* ax = &sJ[i*JSTRIDE + OFF_AX];
        const float* p  = &sJ[i*JSTRIDE + OFF_P];
        const float* Ib = &sJ[i*JSTRIDE + OFF_IB];
        const float* hb = &sJ[i*JSTRIDE + OFF_HB];
        float m = sJ[i*JSTRIDE + OFF_M];
        const float* Am = A[i];
        float xv[6], xa[6];
        applyXup(Am, p, pv, xv);
        applyXup(Am, p, pa, xa);
        float wJ[3] = { ax[0]*qd[i], ax[1]*qd[i], ax[2]*qd[i] };
        float v6[6] = { xv[0]+wJ[0], xv[1]+wJ[1], xv[2]+wJ[2], xv[3], xv[4], xv[5] };
        float cw[3], cl[3];
        cross3(v6, wJ, cw);
        cross3(v6 + 3, wJ, cl);
        float a6[6] = { xa[0]+cw[0], xa[1]+cw[1], xa[2]+cw[2],
                        xa[3]+cl[0], xa[4]+cl[1], xa[5]+cl[2] };
        // I v = (Ib w + hb x l ; m l - hb x w)
        float Ivn[3], Ivf[3], t1[3], t2[3];
        sym3v(Ib, v6, Ivn);
        cross3(hb, v6 + 3, t1);
        cross3(hb, v6, t2);
#pragma unroll
        for (int k = 0; k < 3; k++) { Ivn[k] += t1[k]; Ivf[k] = m * v6[3+k] - t2[k]; }
        float Ian[3], Iaf[3];
        sym3v(Ib, a6, Ian);
        cross3(hb, a6 + 3, t1);
        cross3(hb, a6, t2);
#pragma unroll
        for (int k = 0; k < 3; k++) { Ian[k] += t1[k]; Iaf[k] = m * a6[3+k] - t2[k]; }
        // f = Ia + (w x Ivn + l x Ivf ; w x Ivf)
        float c1[3], c2[3], c3[3];
        cross3(v6, Ivn, c1);
        cross3(v6 + 3, Ivf, c2);
        cross3(v6, Ivf, c3);
#pragma unroll
        for (int k = 0; k < 3; k++) {
            fw[i][k] = Ian[k] + c1[k] + c2[k];
            fv[i][k] = Iaf[k] + c3[k];
        }
#pragma unroll
        for (int k = 0; k < 6; k++) { pv[k] = v6[k]; pa[k] = a6[k]; }
    }

    // ---- backward pass: bb = tau - h ----
#pragma unroll
    for (int i = NJ - 1; i >= 0; i--) {
        const float* ax = &sJ[i*JSTRIDE + OFF_AX];
        bb[i] -= ax[0]*fw[i][0] + ax[1]*fw[i][1] + ax[2]*fw[i][2];
        if (i > 0) {
            float f6[6] = { fw[i][0], fw[i][1], fw[i][2], fv[i][0], fv[i][1], fv[i][2] };
            float o6[6];
            applyXupT(A[i], &sJ[i*JSTRIDE + OFF_P], f6, o6);
#pragma unroll
            for (int k = 0; k < 3; k++) { fw[i-1][k] += o6[k]; fv[i-1][k] += o6[3+k]; }
        }
    }

    // ---- CRBA with 10-parameter composite inertia {Jc sym6, hc3, mc} ----
    float Mm[NJ][NJ];   // lower triangle only
    float Jc[6], hc[3], mc;
    {
        const float* Ib = &sJ[(NJ-1)*JSTRIDE + OFF_IB];
        const float* hb = &sJ[(NJ-1)*JSTRIDE + OFF_HB];
#pragma unroll
        for (int k = 0; k < 6; k++) Jc[k] = Ib[k];
#pragma unroll
        for (int k = 0; k < 3; k++) hc[k] = hb[k];
        mc = sJ[(NJ-1)*JSTRIDE + OFF_M];
    }
#pragma unroll
    for (int i = NJ - 1; i >= 0; i--) {
        const float* ax = &sJ[i*JSTRIDE + OFF_AX];
        // F = Ic * (ax;0) = (Jc ax ; ax x hc)
        float F[6];
        sym3v(Jc, ax, F);
        cross3(ax, hc, F + 3);
        Mm[i][i] = ax[0]*F[0] + ax[1]*F[1] + ax[2]*F[2] + 1e-8f;
#pragma unroll
        for (int j = i - 1; j >= 0; j--) {
            float o6[6];
            applyXupT(A[j+1], &sJ[(j+1)*JSTRIDE + OFF_P], F, o6);
#pragma unroll
            for (int r = 0; r < 6; r++) F[r] = o6[r];
            const float* aj = &sJ[j*JSTRIDE + OFF_AX];
            Mm[i][j] = aj[0]*F[0] + aj[1]*F[1] + aj[2]*F[2];
        }
        if (i > 0) {
            const float* p  = &sJ[i*JSTRIDE + OFF_P];
            const float* Am = A[i];
            // transform composite into parent frame:
            // h' = A^T hc ; J' = A^T Jc A ;
            // J_new = J' + 2(h'.p) I - p h'^T - h' p^T - mc p p^T + mc |p|^2 I
            // h_new = h' + mc p ; m_new = mc
            float hp[3];
            mat3tv(Am, hc, hp);
            // T = Jc(sym) * A  (T[r][c] = sum_k Jc[r][k] A[k][c])
            float T[9];
#pragma unroll
            for (int cc = 0; cc < 3; cc++) {
                T[0*3+cc] = Jc[0]*Am[0*3+cc] + Jc[1]*Am[1*3+cc] + Jc[2]*Am[2*3+cc];
                T[1*3+cc] = Jc[1]*Am[0*3+cc] + Jc[3]*Am[1*3+cc] + Jc[4]*Am[2*3+cc];
                T[2*3+cc] = Jc[2]*Am[0*3+cc] + Jc[4]*Am[1*3+cc] + Jc[5]*Am[2*3+cc];
            }
            // Jp = A^T T, 6 uniques
            float Jp[6];
            Jp[0] = Am[0]*T[0] + Am[3]*T[3] + Am[6]*T[6];
            Jp[1] = Am[0]*T[1] + Am[3]*T[4] + Am[6]*T[7];
            Jp[2] = Am[0]*T[2] + Am[3]*T[5] + Am[6]*T[8];
            Jp[3] = Am[1]*T[1] + Am[4]*T[4] + Am[7]*T[7];
            Jp[4] = Am[1]*T[2] + Am[4]*T[5] + Am[7]*T[8];
            Jp[5] = Am[2]*T[2] + Am[5]*T[5] + Am[8]*T[8];
            float hdp = hp[0]*p[0] + hp[1]*p[1] + hp[2]*p[2];
            float pp  = p[0]*p[0] + p[1]*p[1] + p[2]*p[2];
            float diag = 2.0f*hdp + mc*pp;
            const float* Ibp = &sJ[(i-1)*JSTRIDE + OFF_IB];
            const float* hbp = &sJ[(i-1)*JSTRIDE + OFF_HB];
            Jc[0] = Ibp[0] + Jp[0] + diag - 2.0f*p[0]*hp[0] - mc*p[0]*p[0];
            Jc[1] = Ibp[1] + Jp[1] - (p[0]*hp[1] + hp[0]*p[1]) - mc*p[0]*p[1];
            Jc[2] = Ibp[2] + Jp[2] - (p[0]*hp[2] + hp[0]*p[2]) - mc*p[0]*p[2];
            Jc[3] = Ibp[3] + Jp[3] + diag - 2.0f*p[1]*hp[1] - mc*p[1]*p[1];
            Jc[4] = Ibp[4] + Jp[4] - (p[1]*hp[2] + hp[1]*p[2]) - mc*p[1]*p[2];
            Jc[5] = Ibp[5] + Jp[5] + diag - 2.0f*p[2]*hp[2] - mc*p[2]*p[2];
            hc[0] = hbp[0] + hp[0] + mc*p[0];
            hc[1] = hbp[1] + hp[1] + mc*p[1];
            hc[2] = hbp[2] + hp[2] + mc*p[2];
            mc += sJ[(i-1)*JSTRIDE + OFF_M];
        }
    }

    // ---- symmetric GE on lower triangle: M qdd = bb ----
#pragma unroll
    for (int k = 0; k < NJ; k++) {
        float inv = __fdividef(1.0f, Mm[k][k]);
#pragma unroll
        for (int r = k + 1; r < NJ; r++) {
            float fkt = Mm[r][k] * inv;
#pragma unroll
            for (int c2 = k + 1; c2 <= r; c2++) Mm[r][c2] -= fkt * Mm[c2][k];
            bb[r] -= fkt * bb[k];
        }
    }
    float qdd[NJ];
#pragma unroll
    for (int k = NJ - 1; k >= 0; k--) {
        float t = bb[k];
#pragma unroll
        for (int c2 = k + 1; c2 < NJ; c2++) t -= Mm[c2][k] * qdd[c2];
        qdd[k] = __fdividef(t, Mm[k][k]);
    }

    // ---- integrate & write ----
#pragma unroll
    for (int k = 0; k < NJ; k++) {
        float qdn = qd[k] + DT_ * qdd[k];
        float qn  = q[k] + DT_ * qdn;
        out[b * 14 + k] = qn;
        out[b * 14 + 7 + k] = qdn;
    }
}

extern "C" void kernel_launch(void* const* d_in, const int* in_sizes, int n_in,
                              void* d_out, int out_size) {
    const float* x     = (const float*)d_in[0];
    const float* u     = (const float*)d_in[1];
    const float* axes  = (const float*)d_in[2];
    const float* Rtree = (const float*)d_in[3];
    const float* ptree = (const float*)d_in[4];
    const float* Isp   = (const float*)d_in[5];
    float* out = (float*)d_out;

    int B = in_sizes[0] / 14;
    int blocks = (B + TPB - 1) / TPB;
    panda_dyn_kernel<<<blocks, TPB>>>(x, u, axes, Rtree, ptree, Isp, out, B);
}